// round 2
// baseline (speedup 1.0000x reference)
#include <cuda_runtime.h>
#include <math.h>

#define BATCH   4
#define SEQ     4096
#define DMODEL  1024
#define DHEAD   128
#define NBLOCKS 4.0f

#define NPER (BATCH * SEQ * DHEAD)   // 2,097,152 elements per tensor

// Scratch: Q always lives here; K/V fall back here if d_out only holds `output`.
// NOTE: __device__ symbols are only dereferenced from device code (host code
// cannot take their address — that was the round-1 bug).
__device__ float g_Q[NPER];
__device__ float g_KV[2 * NPER];

// ---------------------------------------------------------------------------
// Kernel 1: fused QKV projection.  Y[m, n] = sum_d x[m,d] * W[n,d] + b[n]
// Logical N = 384 (Q | K | V).  BM=64, BN=64, BK=16, 256 threads, 4x4/thread.
// ---------------------------------------------------------------------------
__global__ __launch_bounds__(256) void qkv_proj_kernel(
    const float* __restrict__ x,
    const float* __restrict__ Wq, const float* __restrict__ bq,
    const float* __restrict__ Wk, const float* __restrict__ bk,
    const float* __restrict__ Wv, const float* __restrict__ bv,
    float* Kout, float* Vout)
{
    __shared__ float As[16][64];   // As[k][m]
    __shared__ float Bs[16][64];   // Bs[k][n]

    if (Kout == nullptr) Kout = g_KV;
    if (Vout == nullptr) Vout = g_KV + NPER;

    const int tid = threadIdx.x;
    const int tx = tid & 15;        // n-group
    const int ty = tid >> 4;        // m-group
    const int m0 = blockIdx.y * 64;
    const int n0g = blockIdx.x * 64;        // 0..383

    const float* W;
    const float* bias;
    float* out;
    int n0;
    if (n0g < 128)      { W = Wq; bias = bq; out = g_Q;  n0 = n0g;       }
    else if (n0g < 256) { W = Wk; bias = bk; out = Kout; n0 = n0g - 128; }
    else                { W = Wv; bias = bv; out = Vout; n0 = n0g - 256; }

    float acc[4][4] = {};

    const int lrow = tid >> 2;        // 0..63
    const int lc   = (tid & 3) * 4;   // 0,4,8,12

    for (int k0 = 0; k0 < DMODEL; k0 += 16) {
        float4 xa = *(const float4*)&x[(size_t)(m0 + lrow) * DMODEL + k0 + lc];
        float4 wb = *(const float4*)&W[(size_t)(n0 + lrow) * DMODEL + k0 + lc];
        __syncthreads();
        As[lc + 0][lrow] = xa.x; As[lc + 1][lrow] = xa.y;
        As[lc + 2][lrow] = xa.z; As[lc + 3][lrow] = xa.w;
        Bs[lc + 0][lrow] = wb.x; Bs[lc + 1][lrow] = wb.y;
        Bs[lc + 2][lrow] = wb.z; Bs[lc + 3][lrow] = wb.w;
        __syncthreads();

        #pragma unroll
        for (int k = 0; k < 16; k++) {
            float4 a = *(const float4*)&As[k][ty * 4];
            float4 b = *(const float4*)&Bs[k][tx * 4];
            float av[4] = {a.x, a.y, a.z, a.w};
            float bv4[4] = {b.x, b.y, b.z, b.w};
            #pragma unroll
            for (int i = 0; i < 4; i++)
                #pragma unroll
                for (int j = 0; j < 4; j++)
                    acc[i][j] += av[i] * bv4[j];
        }
    }

    #pragma unroll
    for (int i = 0; i < 4; i++) {
        float4 o;
        float* dst = &out[(size_t)(m0 + ty * 4 + i) * DHEAD + n0 + tx * 4];
        o.x = acc[i][0] + bias[n0 + tx * 4 + 0];
        o.y = acc[i][1] + bias[n0 + tx * 4 + 1];
        o.z = acc[i][2] + bias[n0 + tx * 4 + 2];
        o.w = acc[i][3] + bias[n0 + tx * 4 + 3];
        *(float4*)dst = o;
    }
}

// ---------------------------------------------------------------------------
// Kernel 2: flash attention, fp32.  Q is read from the __device__ symbol g_Q
// (device-side reference — legal; host-side was not).
// Block = (batch b, 64-query tile). 256 threads (tx in [0,16): key/col group,
// ty in [0,16): query group; each thread owns 4 query rows).
// out = NBLOCKS * softmax(Q K^T / sqrt(128)) V
// ---------------------------------------------------------------------------
__global__ __launch_bounds__(256) void flash_attn_kernel(
    const float* Kin, const float* Vin,
    float* __restrict__ Out)
{
    extern __shared__ float sm[];
    float* Qs = sm;                  // [128][64]  (d-major, transposed)
    float* Ks = Qs + 128 * 64;       // [128][64]  (d-major, transposed)
    float* Vs = Ks + 128 * 64;       // [64][128]  (row-major)
    float* Ps = Vs + 64 * 128;       // [64][64]   (key-major: Ps[j][i])

    const float* Q    = g_Q;
    const float* Kmat = Kin ? Kin : g_KV;
    const float* Vmat = Vin ? Vin : g_KV + NPER;

    const int b  = blockIdx.y;
    const int q0 = blockIdx.x * 64;
    const float* Qb = Q    + (size_t)b * SEQ * DHEAD;
    const float* Kb = Kmat + (size_t)b * SEQ * DHEAD;
    const float* Vb = Vmat + (size_t)b * SEQ * DHEAD;

    const int tid = threadIdx.x;
    const int tx = tid & 15;
    const int ty = tid >> 4;

    // ---- load Q tile transposed: Qs[d][i] ----
    {
        const int r  = tid >> 2;          // 0..63 query row
        const int cb = (tid & 3) * 32;    // 32 d-values per thread
        #pragma unroll
        for (int c = 0; c < 32; c += 4) {
            float4 v = *(const float4*)&Qb[(size_t)(q0 + r) * DHEAD + cb + c];
            Qs[(cb + c + 0) * 64 + r] = v.x;
            Qs[(cb + c + 1) * 64 + r] = v.y;
            Qs[(cb + c + 2) * 64 + r] = v.z;
            Qs[(cb + c + 3) * 64 + r] = v.w;
        }
    }

    float m_[4], l_[4];
    float acc[4][8];
    #pragma unroll
    for (int r = 0; r < 4; r++) {
        m_[r] = -INFINITY; l_[r] = 0.0f;
        #pragma unroll
        for (int c = 0; c < 8; c++) acc[r][c] = 0.0f;
    }

    const float scale = 0.08838834764831845f;   // 1/sqrt(128)

    for (int kt = 0; kt < SEQ; kt += 64) {
        __syncthreads();   // prior PV reads of Ps/Vs and S reads of Ks done
        // ---- load K tile transposed + V tile direct ----
        {
            const int r  = tid >> 2;
            const int cb = (tid & 3) * 32;
            #pragma unroll
            for (int c = 0; c < 32; c += 4) {
                float4 v = *(const float4*)&Kb[(size_t)(kt + r) * DHEAD + cb + c];
                Ks[(cb + c + 0) * 64 + r] = v.x;
                Ks[(cb + c + 1) * 64 + r] = v.y;
                Ks[(cb + c + 2) * 64 + r] = v.z;
                Ks[(cb + c + 3) * 64 + r] = v.w;
            }
            const float4* Vsrc = (const float4*)&Vb[(size_t)kt * DHEAD];
            float4* Vdst = (float4*)Vs;
            #pragma unroll
            for (int i = 0; i < 8; i++)
                Vdst[tid + i * 256] = Vsrc[tid + i * 256];
        }
        __syncthreads();

        // ---- S = (Q K^T) * scale : 4x4 per thread ----
        float s[4][4] = {};
        #pragma unroll 4
        for (int d = 0; d < 128; d++) {
            float4 a  = *(const float4*)&Qs[d * 64 + ty * 4];
            float4 k4 = *(const float4*)&Ks[d * 64 + tx * 4];
            float av[4] = {a.x, a.y, a.z, a.w};
            float kv[4] = {k4.x, k4.y, k4.z, k4.w};
            #pragma unroll
            for (int i = 0; i < 4; i++)
                #pragma unroll
                for (int j = 0; j < 4; j++)
                    s[i][j] += av[i] * kv[j];
        }

        // ---- online softmax per row; write P tile (key-major) ----
        #pragma unroll
        for (int r = 0; r < 4; r++) {
            float mx = -INFINITY;
            #pragma unroll
            for (int j = 0; j < 4; j++) {
                s[r][j] *= scale;
                mx = fmaxf(mx, s[r][j]);
            }
            #pragma unroll
            for (int w = 8; w >= 1; w >>= 1)
                mx = fmaxf(mx, __shfl_xor_sync(0xffffffffu, mx, w));
            float mnew = fmaxf(m_[r], mx);
            float corr = __expf(m_[r] - mnew);
            float rs = 0.0f;
            #pragma unroll
            for (int j = 0; j < 4; j++) {
                float p = __expf(s[r][j] - mnew);
                s[r][j] = p;
                rs += p;
            }
            #pragma unroll
            for (int w = 8; w >= 1; w >>= 1)
                rs += __shfl_xor_sync(0xffffffffu, rs, w);
            l_[r] = l_[r] * corr + rs;
            m_[r] = mnew;
            #pragma unroll
            for (int c = 0; c < 8; c++) acc[r][c] *= corr;
            #pragma unroll
            for (int j = 0; j < 4; j++)
                Ps[(tx * 4 + j) * 64 + ty * 4 + r] = s[r][j];
        }
        __syncthreads();

        // ---- acc += P V : 4 rows x 8 cols per thread ----
        const int c0 = tx * 8;
        #pragma unroll 4
        for (int j = 0; j < 64; j++) {
            float4 p  = *(const float4*)&Ps[j * 64 + ty * 4];
            float4 v0 = *(const float4*)&Vs[j * 128 + c0];
            float4 v1 = *(const float4*)&Vs[j * 128 + c0 + 4];
            float pv[4] = {p.x, p.y, p.z, p.w};
            float vv[8] = {v0.x, v0.y, v0.z, v0.w, v1.x, v1.y, v1.z, v1.w};
            #pragma unroll
            for (int r = 0; r < 4; r++)
                #pragma unroll
                for (int c = 0; c < 8; c++)
                    acc[r][c] += pv[r] * vv[c];
        }
    }

    // ---- epilogue: out = NBLOCKS * acc / l ----
    float* Ob = Out + (size_t)b * SEQ * DHEAD;
    #pragma unroll
    for (int r = 0; r < 4; r++) {
        float inv = NBLOCKS / l_[r];
        float* dst = &Ob[(size_t)(q0 + ty * 4 + r) * DHEAD + tx * 8];
        float4 o0, o1;
        o0.x = acc[r][0] * inv; o0.y = acc[r][1] * inv;
        o0.z = acc[r][2] * inv; o0.w = acc[r][3] * inv;
        o1.x = acc[r][4] * inv; o1.y = acc[r][5] * inv;
        o1.z = acc[r][6] * inv; o1.w = acc[r][7] * inv;
        *(float4*)dst = o0;
        *(float4*)(dst + 4) = o1;
    }
}

// ---------------------------------------------------------------------------
extern "C" void kernel_launch(void* const* d_in, const int* in_sizes, int n_in,
                              void* d_out, int out_size)
{
    const float* x  = (const float*)d_in[0];
    const float* Wq = (const float*)d_in[1];
    const float* bq = (const float*)d_in[2];
    const float* Wk = (const float*)d_in[3];
    const float* bk = (const float*)d_in[4];
    const float* Wv = (const float*)d_in[5];
    const float* bv = (const float*)d_in[6];
    // d_in[7] = block_idx (unused: reference accumulates NUM_BLOCKS identical blocks)

    float* out = (float*)d_out;
    float* Kout = nullptr;
    float* Vout = nullptr;
    if (out_size >= 3 * NPER) {          // tuple (output, K, V) concatenated
        Kout = out + NPER;
        Vout = out + 2 * NPER;
    }

    // QKV projection: grid (384/64 n-tiles, 16384/64 m-tiles)
    dim3 g1(6, 256);
    qkv_proj_kernel<<<g1, 256>>>(x, Wq, bq, Wk, bk, Wv, bv, Kout, Vout);

    // Flash attention
    const int smem = (128 * 64 + 128 * 64 + 64 * 128 + 64 * 64) * (int)sizeof(float); // 114688
    cudaFuncSetAttribute(flash_attn_kernel,
                         cudaFuncAttributeMaxDynamicSharedMemorySize, smem);
    dim3 g2(SEQ / 64, BATCH);
    flash_attn_kernel<<<g2, 256, smem>>>(Kout, Vout, out);
}

// round 3
// speedup vs baseline: 1.0016x; 1.0016x over previous
#include <cuda_runtime.h>
#include <math.h>

#define BATCH   4
#define SEQ     4096
#define DMODEL  1024
#define DHEAD   128
#define NBLOCKS 4.0f

#define NPER (BATCH * SEQ * DHEAD)   // 2,097,152 elements per tensor

// Scratch: Q always lives here; K/V fall back here if d_out only holds `output`.
// NOTE: __device__ symbols are only dereferenced from device code (host code
// cannot take their address — that was the round-1 bug).
__device__ float g_Q[NPER];
__device__ float g_KV[2 * NPER];

// ---------------------------------------------------------------------------
// Kernel 1: fused QKV projection.  Y[m, n] = sum_d x[m,d] * W[n,d] + b[n]
// Logical N = 384 (Q | K | V).  BM=64, BN=64, BK=16, 256 threads, 4x4/thread.
// ---------------------------------------------------------------------------
__global__ __launch_bounds__(256) void qkv_proj_kernel(
    const float* __restrict__ x,
    const float* __restrict__ Wq, const float* __restrict__ bq,
    const float* __restrict__ Wk, const float* __restrict__ bk,
    const float* __restrict__ Wv, const float* __restrict__ bv,
    float* Kout, float* Vout)
{
    __shared__ float As[16][64];   // As[k][m]
    __shared__ float Bs[16][64];   // Bs[k][n]

    if (Kout == nullptr) Kout = g_KV;
    if (Vout == nullptr) Vout = g_KV + NPER;

    const int tid = threadIdx.x;
    const int tx = tid & 15;        // n-group
    const int ty = tid >> 4;        // m-group
    const int m0 = blockIdx.y * 64;
    const int n0g = blockIdx.x * 64;        // 0..383

    const float* W;
    const float* bias;
    float* out;
    int n0;
    if (n0g < 128)      { W = Wq; bias = bq; out = g_Q;  n0 = n0g;       }
    else if (n0g < 256) { W = Wk; bias = bk; out = Kout; n0 = n0g - 128; }
    else                { W = Wv; bias = bv; out = Vout; n0 = n0g - 256; }

    float acc[4][4] = {};

    const int lrow = tid >> 2;        // 0..63
    const int lc   = (tid & 3) * 4;   // 0,4,8,12

    for (int k0 = 0; k0 < DMODEL; k0 += 16) {
        float4 xa = *(const float4*)&x[(size_t)(m0 + lrow) * DMODEL + k0 + lc];
        float4 wb = *(const float4*)&W[(size_t)(n0 + lrow) * DMODEL + k0 + lc];
        __syncthreads();
        As[lc + 0][lrow] = xa.x; As[lc + 1][lrow] = xa.y;
        As[lc + 2][lrow] = xa.z; As[lc + 3][lrow] = xa.w;
        Bs[lc + 0][lrow] = wb.x; Bs[lc + 1][lrow] = wb.y;
        Bs[lc + 2][lrow] = wb.z; Bs[lc + 3][lrow] = wb.w;
        __syncthreads();

        #pragma unroll
        for (int k = 0; k < 16; k++) {
            float4 a = *(const float4*)&As[k][ty * 4];
            float4 b = *(const float4*)&Bs[k][tx * 4];
            float av[4] = {a.x, a.y, a.z, a.w};
            float bv4[4] = {b.x, b.y, b.z, b.w};
            #pragma unroll
            for (int i = 0; i < 4; i++)
                #pragma unroll
                for (int j = 0; j < 4; j++)
                    acc[i][j] += av[i] * bv4[j];
        }
    }

    #pragma unroll
    for (int i = 0; i < 4; i++) {
        float4 o;
        float* dst = &out[(size_t)(m0 + ty * 4 + i) * DHEAD + n0 + tx * 4];
        o.x = acc[i][0] + bias[n0 + tx * 4 + 0];
        o.y = acc[i][1] + bias[n0 + tx * 4 + 1];
        o.z = acc[i][2] + bias[n0 + tx * 4 + 2];
        o.w = acc[i][3] + bias[n0 + tx * 4 + 3];
        *(float4*)dst = o;
    }
}

// ---------------------------------------------------------------------------
// Kernel 2: flash attention, fp32.  Q is read from the __device__ symbol g_Q
// (device-side reference — legal; host-side was not).
// Block = (batch b, 64-query tile). 256 threads (tx in [0,16): key/col group,
// ty in [0,16): query group; each thread owns 4 query rows).
// out = NBLOCKS * softmax(Q K^T / sqrt(128)) V
// ---------------------------------------------------------------------------
__global__ __launch_bounds__(256) void flash_attn_kernel(
    const float* Kin, const float* Vin,
    float* __restrict__ Out)
{
    extern __shared__ float sm[];
    float* Qs = sm;                  // [128][64]  (d-major, transposed)
    float* Ks = Qs + 128 * 64;       // [128][64]  (d-major, transposed)
    float* Vs = Ks + 128 * 64;       // [64][128]  (row-major)
    float* Ps = Vs + 64 * 128;       // [64][64]   (key-major: Ps[j][i])

    const float* Q    = g_Q;
    const float* Kmat = Kin ? Kin : g_KV;
    const float* Vmat = Vin ? Vin : g_KV + NPER;

    const int b  = blockIdx.y;
    const int q0 = blockIdx.x * 64;
    const float* Qb = Q    + (size_t)b * SEQ * DHEAD;
    const float* Kb = Kmat + (size_t)b * SEQ * DHEAD;
    const float* Vb = Vmat + (size_t)b * SEQ * DHEAD;

    const int tid = threadIdx.x;
    const int tx = tid & 15;
    const int ty = tid >> 4;

    // ---- load Q tile transposed: Qs[d][i] ----
    {
        const int r  = tid >> 2;          // 0..63 query row
        const int cb = (tid & 3) * 32;    // 32 d-values per thread
        #pragma unroll
        for (int c = 0; c < 32; c += 4) {
            float4 v = *(const float4*)&Qb[(size_t)(q0 + r) * DHEAD + cb + c];
            Qs[(cb + c + 0) * 64 + r] = v.x;
            Qs[(cb + c + 1) * 64 + r] = v.y;
            Qs[(cb + c + 2) * 64 + r] = v.z;
            Qs[(cb + c + 3) * 64 + r] = v.w;
        }
    }

    float m_[4], l_[4];
    float acc[4][8];
    #pragma unroll
    for (int r = 0; r < 4; r++) {
        m_[r] = -INFINITY; l_[r] = 0.0f;
        #pragma unroll
        for (int c = 0; c < 8; c++) acc[r][c] = 0.0f;
    }

    const float scale = 0.08838834764831845f;   // 1/sqrt(128)

    for (int kt = 0; kt < SEQ; kt += 64) {
        __syncthreads();   // prior PV reads of Ps/Vs and S reads of Ks done
        // ---- load K tile transposed + V tile direct ----
        {
            const int r  = tid >> 2;
            const int cb = (tid & 3) * 32;
            #pragma unroll
            for (int c = 0; c < 32; c += 4) {
                float4 v = *(const float4*)&Kb[(size_t)(kt + r) * DHEAD + cb + c];
                Ks[(cb + c + 0) * 64 + r] = v.x;
                Ks[(cb + c + 1) * 64 + r] = v.y;
                Ks[(cb + c + 2) * 64 + r] = v.z;
                Ks[(cb + c + 3) * 64 + r] = v.w;
            }
            const float4* Vsrc = (const float4*)&Vb[(size_t)kt * DHEAD];
            float4* Vdst = (float4*)Vs;
            #pragma unroll
            for (int i = 0; i < 8; i++)
                Vdst[tid + i * 256] = Vsrc[tid + i * 256];
        }
        __syncthreads();

        // ---- S = (Q K^T) * scale : 4x4 per thread ----
        float s[4][4] = {};
        #pragma unroll 4
        for (int d = 0; d < 128; d++) {
            float4 a  = *(const float4*)&Qs[d * 64 + ty * 4];
            float4 k4 = *(const float4*)&Ks[d * 64 + tx * 4];
            float av[4] = {a.x, a.y, a.z, a.w};
            float kv[4] = {k4.x, k4.y, k4.z, k4.w};
            #pragma unroll
            for (int i = 0; i < 4; i++)
                #pragma unroll
                for (int j = 0; j < 4; j++)
                    s[i][j] += av[i] * kv[j];
        }

        // ---- online softmax per row; write P tile (key-major) ----
        #pragma unroll
        for (int r = 0; r < 4; r++) {
            float mx = -INFINITY;
            #pragma unroll
            for (int j = 0; j < 4; j++) {
                s[r][j] *= scale;
                mx = fmaxf(mx, s[r][j]);
            }
            #pragma unroll
            for (int w = 8; w >= 1; w >>= 1)
                mx = fmaxf(mx, __shfl_xor_sync(0xffffffffu, mx, w));
            float mnew = fmaxf(m_[r], mx);
            float corr = __expf(m_[r] - mnew);
            float rs = 0.0f;
            #pragma unroll
            for (int j = 0; j < 4; j++) {
                float p = __expf(s[r][j] - mnew);
                s[r][j] = p;
                rs += p;
            }
            #pragma unroll
            for (int w = 8; w >= 1; w >>= 1)
                rs += __shfl_xor_sync(0xffffffffu, rs, w);
            l_[r] = l_[r] * corr + rs;
            m_[r] = mnew;
            #pragma unroll
            for (int c = 0; c < 8; c++) acc[r][c] *= corr;
            #pragma unroll
            for (int j = 0; j < 4; j++)
                Ps[(tx * 4 + j) * 64 + ty * 4 + r] = s[r][j];
        }
        __syncthreads();

        // ---- acc += P V : 4 rows x 8 cols per thread ----
        const int c0 = tx * 8;
        #pragma unroll 4
        for (int j = 0; j < 64; j++) {
            float4 p  = *(const float4*)&Ps[j * 64 + ty * 4];
            float4 v0 = *(const float4*)&Vs[j * 128 + c0];
            float4 v1 = *(const float4*)&Vs[j * 128 + c0 + 4];
            float pv[4] = {p.x, p.y, p.z, p.w};
            float vv[8] = {v0.x, v0.y, v0.z, v0.w, v1.x, v1.y, v1.z, v1.w};
            #pragma unroll
            for (int r = 0; r < 4; r++)
                #pragma unroll
                for (int c = 0; c < 8; c++)
                    acc[r][c] += pv[r] * vv[c];
        }
    }

    // ---- epilogue: out = NBLOCKS * acc / l ----
    float* Ob = Out + (size_t)b * SEQ * DHEAD;
    #pragma unroll
    for (int r = 0; r < 4; r++) {
        float inv = NBLOCKS / l_[r];
        float* dst = &Ob[(size_t)(q0 + ty * 4 + r) * DHEAD + tx * 8];
        float4 o0, o1;
        o0.x = acc[r][0] * inv; o0.y = acc[r][1] * inv;
        o0.z = acc[r][2] * inv; o0.w = acc[r][3] * inv;
        o1.x = acc[r][4] * inv; o1.y = acc[r][5] * inv;
        o1.z = acc[r][6] * inv; o1.w = acc[r][7] * inv;
        *(float4*)dst = o0;
        *(float4*)(dst + 4) = o1;
    }
}

// ---------------------------------------------------------------------------
extern "C" void kernel_launch(void* const* d_in, const int* in_sizes, int n_in,
                              void* d_out, int out_size)
{
    const float* x  = (const float*)d_in[0];
    const float* Wq = (const float*)d_in[1];
    const float* bq = (const float*)d_in[2];
    const float* Wk = (const float*)d_in[3];
    const float* bk = (const float*)d_in[4];
    const float* Wv = (const float*)d_in[5];
    const float* bv = (const float*)d_in[6];
    // d_in[7] = block_idx (unused: reference accumulates NUM_BLOCKS identical blocks)

    float* out = (float*)d_out;
    float* Kout = nullptr;
    float* Vout = nullptr;
    if (out_size >= 3 * NPER) {          // tuple (output, K, V) concatenated
        Kout = out + NPER;
        Vout = out + 2 * NPER;
    }

    // QKV projection: grid (384/64 n-tiles, 16384/64 m-tiles)
    dim3 g1(6, 256);
    qkv_proj_kernel<<<g1, 256>>>(x, Wq, bq, Wk, bk, Wv, bv, Kout, Vout);

    // Flash attention
    const int smem = (128 * 64 + 128 * 64 + 64 * 128 + 64 * 64) * (int)sizeof(float); // 114688
    cudaFuncSetAttribute(flash_attn_kernel,
                         cudaFuncAttributeMaxDynamicSharedMemorySize, smem);
    dim3 g2(SEQ / 64, BATCH);
    flash_attn_kernel<<<g2, 256, smem>>>(Kout, Vout, out);
}

// round 5
// speedup vs baseline: 2.6828x; 2.6786x over previous
#include <cuda_runtime.h>
#include <stdint.h>
#include <math.h>

#define BATCH   4
#define SEQ     4096
#define DMODEL  1024
#define DHEAD   128
#define NPER    (BATCH*SEQ*DHEAD)
#define SCALE   0.08838834764831845f   // 1/sqrt(128)
#define NBLOCKS 4.0f

// Scratch (device globals; addresses via cudaGetSymbolAddress on host)
__device__ float g_Q[NPER];                        // 8 MB
__device__ float g_Vt[NPER];                       // 8 MB (V transposed, [b][v][m])
__device__ float g_S[(size_t)BATCH*SEQ*SEQ];       // 256 MB scores/probs
__device__ float g_KV[2*NPER];                     // fallback if d_out lacks K/V

__device__ __forceinline__ uint32_t f2tf32(float f){
    uint32_t r; asm("cvt.rna.tf32.f32 %0, %1;" : "=r"(r) : "f"(f)); return r;
}

// ---------------- GEMM via mma.sync m16n8k8 tf32 (sm_80+ ISA, no 'a' target) ---
// C[M,N] = A . B^T (+bias).  A:[M,K] K-major, B:[N,K] K-major.  CTA tile 128x128,
// 8 warps (2 m x 4 n), warp tile 64x32.  K chunk 32, double-buffered smem.
#define LDK      36                       // padded row stride in floats (144B: 16B-aligned, conflict-free frags)
#define TILE_F   (128*LDK)                // 4608 floats per operand tile
#define STAGE_F  (2*TILE_F)               // A tile + B tile
#define SMEM_BYTES (2*STAGE_F*4)          // 73728 B (double buffered)

__device__ __forceinline__ void gemm_tile_mma(
    const float* __restrict__ A, int lda,
    const float* __restrict__ B, int ldb,
    float* __restrict__ C, int ldc,
    int Ktot, const float* bias, int m0, int n0)
{
    extern __shared__ uint32_t smbuf[];
    uint32_t* const AsBuf[2] = { smbuf,            smbuf + STAGE_F };
    uint32_t* const BsBuf[2] = { smbuf + TILE_F,   smbuf + STAGE_F + TILE_F };

    const int tid  = threadIdx.x;
    const int lane = tid & 31;
    const int warp = tid >> 5;
    const int wm = warp >> 2;       // 0..1  (m 64-row half)
    const int wn = warp & 3;        // 0..3  (n 32-col quarter)
    const int g  = lane >> 2;       // 0..7
    const int tg = lane & 3;        // 0..3

    // global->smem mapping: thread covers rows r0, r0+32, r0+64, r0+96; quad q (4 floats)
    const int r0 = tid >> 3;        // 0..31
    const int q  = tid & 7;         // 0..7
    const float* Ap = A + (size_t)(m0 + r0) * lda + q*4;
    const float* Bp = B + (size_t)(n0 + r0) * ldb + q*4;

    float c[4][4][4];
    #pragma unroll
    for (int i=0;i<4;i++)
        #pragma unroll
        for (int j=0;j<4;j++)
            #pragma unroll
            for (int k=0;k<4;k++) c[i][j][k]=0.f;

    const int nIter = Ktot >> 5;

    float4 pa[4], pb[4];
    #pragma unroll
    for (int i=0;i<4;i++){
        pa[i] = *(const float4*)(Ap + (size_t)(32*i)*lda);
        pb[i] = *(const float4*)(Bp + (size_t)(32*i)*ldb);
    }
    #pragma unroll
    for (int i=0;i<4;i++){
        uint32_t* d = AsBuf[0] + (r0+32*i)*LDK + q*4;
        d[0]=f2tf32(pa[i].x); d[1]=f2tf32(pa[i].y); d[2]=f2tf32(pa[i].z); d[3]=f2tf32(pa[i].w);
        uint32_t* e = BsBuf[0] + (r0+32*i)*LDK + q*4;
        e[0]=f2tf32(pb[i].x); e[1]=f2tf32(pb[i].y); e[2]=f2tf32(pb[i].z); e[3]=f2tf32(pb[i].w);
    }
    __syncthreads();

    for (int t=0; t<nIter; t++){
        const int cur = t & 1;
        if (t+1 < nIter){
            const float* Aq = Ap + (t+1)*32;
            const float* Bq = Bp + (t+1)*32;
            #pragma unroll
            for (int i=0;i<4;i++){
                pa[i] = *(const float4*)(Aq + (size_t)(32*i)*lda);
                pb[i] = *(const float4*)(Bq + (size_t)(32*i)*ldb);
            }
        }
        const uint32_t* Ab = AsBuf[cur] + (wm*64)*LDK;
        const uint32_t* Bb = BsBuf[cur] + (wn*32)*LDK;
        #pragma unroll
        for (int ks=0; ks<4; ks++){
            const int cb = ks*8;
            uint32_t a[4][4], b[4][2];
            #pragma unroll
            for (int mi=0; mi<4; mi++){
                const uint32_t* p = Ab + (mi*16+g)*LDK + cb + tg;
                a[mi][0] = p[0];
                a[mi][1] = p[8*LDK];
                a[mi][2] = p[4];
                a[mi][3] = p[8*LDK+4];
            }
            #pragma unroll
            for (int ni=0; ni<4; ni++){
                const uint32_t* p = Bb + (ni*8+g)*LDK + cb + tg;
                b[ni][0] = p[0];
                b[ni][1] = p[4];
            }
            #pragma unroll
            for (int mi=0; mi<4; mi++)
                #pragma unroll
                for (int ni=0; ni<4; ni++)
                    asm volatile(
                        "mma.sync.aligned.m16n8k8.row.col.f32.tf32.tf32.f32 "
                        "{%0,%1,%2,%3}, {%4,%5,%6,%7}, {%8,%9}, {%0,%1,%2,%3};"
                        : "+f"(c[mi][ni][0]), "+f"(c[mi][ni][1]),
                          "+f"(c[mi][ni][2]), "+f"(c[mi][ni][3])
                        : "r"(a[mi][0]), "r"(a[mi][1]), "r"(a[mi][2]), "r"(a[mi][3]),
                          "r"(b[ni][0]), "r"(b[ni][1]));
        }
        if (t+1 < nIter){
            const int nxt = cur ^ 1;
            #pragma unroll
            for (int i=0;i<4;i++){
                uint32_t* d = AsBuf[nxt] + (r0+32*i)*LDK + q*4;
                d[0]=f2tf32(pa[i].x); d[1]=f2tf32(pa[i].y); d[2]=f2tf32(pa[i].z); d[3]=f2tf32(pa[i].w);
                uint32_t* e = BsBuf[nxt] + (r0+32*i)*LDK + q*4;
                e[0]=f2tf32(pb[i].x); e[1]=f2tf32(pb[i].y); e[2]=f2tf32(pb[i].z); e[3]=f2tf32(pb[i].w);
            }
        }
        __syncthreads();
    }

    // epilogue: c frag (mi,ni): rows rowb+mi*16+g (+8), cols colb+ni*8+tg*2 (+1)
    const int rowb = m0 + wm*64;
    const int colb = n0 + wn*32;
    #pragma unroll
    for (int mi=0;mi<4;mi++){
        #pragma unroll
        for (int ni=0;ni<4;ni++){
            const int col = colb + ni*8 + tg*2;
            float b0 = 0.f, b1 = 0.f;
            if (bias){ b0 = bias[col]; b1 = bias[col+1]; }
            float* p0 = C + (size_t)(rowb + mi*16 + g)     * ldc + col;
            float* p1 = C + (size_t)(rowb + mi*16 + g + 8) * ldc + col;
            *(float2*)p0 = make_float2(c[mi][ni][0]+b0, c[mi][ni][1]+b1);
            *(float2*)p1 = make_float2(c[mi][ni][2]+b0, c[mi][ni][3]+b1);
        }
    }
}

// ---------------- kernels ----------------
__global__ __launch_bounds__(256) void proj_kernel(
    const float* __restrict__ x,
    const float* __restrict__ Wq, const float* __restrict__ bq,
    const float* __restrict__ Wk, const float* __restrict__ bk,
    const float* __restrict__ Wv, const float* __restrict__ bv,
    float* Qs, float* Kout, float* Vout)
{
    const float* W; const float* bias; float* C;
    if (blockIdx.x == 0)      { W = Wq; bias = bq; C = Qs;   }
    else if (blockIdx.x == 1) { W = Wk; bias = bk; C = Kout; }
    else                      { W = Wv; bias = bv; C = Vout; }
    gemm_tile_mma(x, DMODEL, W, DMODEL, C, DHEAD, DMODEL, bias, blockIdx.y * 128, 0);
}

__global__ __launch_bounds__(256) void gemm_nt_batched(
    const float* A, int lda, long long sA,
    const float* B, int ldb, long long sB,
    float* C, int ldc, long long sC, int Ktot)
{
    gemm_tile_mma(A + (size_t)blockIdx.z * sA, lda,
                  B + (size_t)blockIdx.z * sB, ldb,
                  C + (size_t)blockIdx.z * sC, ldc,
                  Ktot, nullptr, blockIdx.y * 128, blockIdx.x * 128);
}

__global__ void transpose_v_kernel(const float* __restrict__ V, float* __restrict__ Vt)
{
    __shared__ float tile[32][33];
    const int b  = blockIdx.z;
    const int m0 = blockIdx.x * 32, v0 = blockIdx.y * 32;
    const float* Vb  = V  + (size_t)b * SEQ * DHEAD;
    float*       Vtb = Vt + (size_t)b * DHEAD * SEQ;
    const int tx = threadIdx.x, ty = threadIdx.y;
    #pragma unroll
    for (int i = 0; i < 32; i += 8)
        tile[ty + i][tx] = Vb[(size_t)(m0 + ty + i) * DHEAD + v0 + tx];
    __syncthreads();
    #pragma unroll
    for (int i = 0; i < 32; i += 8)
        Vtb[(size_t)(v0 + ty + i) * SEQ + m0 + tx] = tile[tx][ty + i];
}

// In-place row softmax (rows of 4096); applies SCALE and folds NBLOCKS.
__global__ __launch_bounds__(256) void softmax_kernel(float* __restrict__ S)
{
    __shared__ float red[8];
    float* p = S + ((size_t)blockIdx.y * SEQ + blockIdx.x) * SEQ;
    const int tid = threadIdx.x;
    float4 v[4];
    float mx = -INFINITY;
    #pragma unroll
    for (int i = 0; i < 4; i++) {
        float4 t = ((const float4*)p)[tid + 256 * i];
        t.x *= SCALE; t.y *= SCALE; t.z *= SCALE; t.w *= SCALE;
        v[i] = t;
        mx = fmaxf(mx, fmaxf(fmaxf(t.x, t.y), fmaxf(t.z, t.w)));
    }
    #pragma unroll
    for (int o = 16; o >= 1; o >>= 1) mx = fmaxf(mx, __shfl_xor_sync(~0u, mx, o));
    if ((tid & 31) == 0) red[tid >> 5] = mx;
    __syncthreads();
    const float m = fmaxf(fmaxf(fmaxf(red[0], red[1]), fmaxf(red[2], red[3])),
                          fmaxf(fmaxf(red[4], red[5]), fmaxf(red[6], red[7])));
    float s = 0.0f;
    #pragma unroll
    for (int i = 0; i < 4; i++) {
        v[i].x = __expf(v[i].x - m); v[i].y = __expf(v[i].y - m);
        v[i].z = __expf(v[i].z - m); v[i].w = __expf(v[i].w - m);
        s += v[i].x + v[i].y + v[i].z + v[i].w;
    }
    #pragma unroll
    for (int o = 16; o >= 1; o >>= 1) s += __shfl_xor_sync(~0u, s, o);
    __syncthreads();
    if ((tid & 31) == 0) red[tid >> 5] = s;
    __syncthreads();
    const float S_ = red[0]+red[1]+red[2]+red[3]+red[4]+red[5]+red[6]+red[7];
    const float f = NBLOCKS / S_;
    #pragma unroll
    for (int i = 0; i < 4; i++) {
        v[i].x *= f; v[i].y *= f; v[i].z *= f; v[i].w *= f;
        ((float4*)p)[tid + 256 * i] = v[i];
    }
}

// ---------------- launch ----------------
extern "C" void kernel_launch(void* const* d_in, const int* in_sizes, int n_in,
                              void* d_out, int out_size)
{
    const float* x  = (const float*)d_in[0];
    const float* Wq = (const float*)d_in[1];
    const float* bq = (const float*)d_in[2];
    const float* Wk = (const float*)d_in[3];
    const float* bk = (const float*)d_in[4];
    const float* Wv = (const float*)d_in[5];
    const float* bv = (const float*)d_in[6];

    float* out = (float*)d_out;
    float *qs, *vt, *sc, *gkv;
    cudaGetSymbolAddress((void**)&qs,  g_Q);
    cudaGetSymbolAddress((void**)&vt,  g_Vt);
    cudaGetSymbolAddress((void**)&sc,  g_S);
    cudaGetSymbolAddress((void**)&gkv, g_KV);

    float *Kout, *Vout;
    if (out_size >= 3 * NPER) { Kout = out + NPER; Vout = out + 2 * NPER; }
    else                      { Kout = gkv;        Vout = gkv + NPER;     }

    cudaFuncSetAttribute(proj_kernel,     cudaFuncAttributeMaxDynamicSharedMemorySize, SMEM_BYTES);
    cudaFuncSetAttribute(gemm_nt_batched, cudaFuncAttributeMaxDynamicSharedMemorySize, SMEM_BYTES);

    // 1) QKV projection  (3 weights x 128 m-tiles; N=128 fits one CTA tile)
    proj_kernel<<<dim3(3, 128, 1), 256, SMEM_BYTES>>>(x, Wq, bq, Wk, bk, Wv, bv,
                                                      qs, Kout, Vout);
    // 2) V transpose -> [b][v][m]
    transpose_v_kernel<<<dim3(SEQ/32, DHEAD/32, BATCH), dim3(32, 8)>>>(Vout, vt);
    // 3) S = Q K^T
    gemm_nt_batched<<<dim3(SEQ/128, SEQ/128, BATCH), 256, SMEM_BYTES>>>(
        qs,   DHEAD, (long long)SEQ * DHEAD,
        Kout, DHEAD, (long long)SEQ * DHEAD,
        sc,   SEQ,   (long long)SEQ * SEQ, DHEAD);
    // 4) P = NBLOCKS * softmax(S * scale), in place
    softmax_kernel<<<dim3(SEQ, BATCH), 256>>>(sc);
    // 5) O = P V  (B operand = V^T, K-major over m)
    gemm_nt_batched<<<dim3(1, SEQ/128, BATCH), 256, SMEM_BYTES>>>(
        sc,  SEQ, (long long)SEQ * SEQ,
        vt,  SEQ, (long long)DHEAD * SEQ,
        out, DHEAD, (long long)SEQ * DHEAD, SEQ);
}

// round 6
// speedup vs baseline: 4.3100x; 1.6065x over previous
#include <cuda_runtime.h>
#include <stdint.h>
#include <math.h>

#define BATCH   4
#define SEQ     4096
#define DMODEL  1024
#define DHEAD   128
#define NPER    (BATCH*SEQ*DHEAD)
#define SCALE   0.08838834764831845f   // 1/sqrt(128)
#define NBLOCKS 4.0f
#define NEG_INF (-1e30f)

// Scratch (device globals; addresses via cudaGetSymbolAddress on host)
__device__ float g_Q[NPER];          // 8 MB
__device__ float g_Vt[NPER];         // 8 MB (V transposed, [b][d][m])
__device__ float g_KV[2*NPER];       // fallback if d_out lacks K/V

__device__ __forceinline__ uint32_t f2tf32(float f){
    uint32_t r; asm("cvt.rna.tf32.f32 %0, %1;" : "=r"(r) : "f"(f)); return r;
}
__device__ __forceinline__ void mma8(float* c, const uint32_t* a, uint32_t b0, uint32_t b1){
    asm volatile("mma.sync.aligned.m16n8k8.row.col.f32.tf32.tf32.f32 "
        "{%0,%1,%2,%3}, {%4,%5,%6,%7}, {%8,%9}, {%0,%1,%2,%3};"
        : "+f"(c[0]), "+f"(c[1]), "+f"(c[2]), "+f"(c[3])
        : "r"(a[0]), "r"(a[1]), "r"(a[2]), "r"(a[3]), "r"(b0), "r"(b1));
}

// ================= QKV projection GEMM (round-5, proven) =================
#define LDK      36
#define TILE_F   (128*LDK)
#define STAGE_F  (2*TILE_F)
#define SMEM_PROJ (2*STAGE_F*4)

__device__ __forceinline__ void gemm_tile_mma(
    const float* __restrict__ A, int lda,
    const float* __restrict__ B, int ldb,
    float* __restrict__ C, int ldc,
    int Ktot, const float* bias, int m0, int n0)
{
    extern __shared__ uint32_t smbuf[];
    uint32_t* const AsBuf[2] = { smbuf,          smbuf + STAGE_F };
    uint32_t* const BsBuf[2] = { smbuf + TILE_F, smbuf + STAGE_F + TILE_F };

    const int tid  = threadIdx.x;
    const int lane = tid & 31;
    const int warp = tid >> 5;
    const int wm = warp >> 2, wn = warp & 3;
    const int g  = lane >> 2, tg = lane & 3;
    const int r0 = tid >> 3, q = tid & 7;
    const float* Ap = A + (size_t)(m0 + r0) * lda + q*4;
    const float* Bp = B + (size_t)(n0 + r0) * ldb + q*4;

    float c[4][4][4];
    #pragma unroll
    for (int i=0;i<4;i++) for (int j=0;j<4;j++) for (int k=0;k<4;k++) c[i][j][k]=0.f;

    const int nIter = Ktot >> 5;
    float4 pa[4], pb[4];
    #pragma unroll
    for (int i=0;i<4;i++){
        pa[i] = *(const float4*)(Ap + (size_t)(32*i)*lda);
        pb[i] = *(const float4*)(Bp + (size_t)(32*i)*ldb);
    }
    #pragma unroll
    for (int i=0;i<4;i++){
        uint32_t* d = AsBuf[0] + (r0+32*i)*LDK + q*4;
        d[0]=f2tf32(pa[i].x); d[1]=f2tf32(pa[i].y); d[2]=f2tf32(pa[i].z); d[3]=f2tf32(pa[i].w);
        uint32_t* e = BsBuf[0] + (r0+32*i)*LDK + q*4;
        e[0]=f2tf32(pb[i].x); e[1]=f2tf32(pb[i].y); e[2]=f2tf32(pb[i].z); e[3]=f2tf32(pb[i].w);
    }
    __syncthreads();

    for (int t=0; t<nIter; t++){
        const int cur = t & 1;
        if (t+1 < nIter){
            const float* Aq = Ap + (t+1)*32;
            const float* Bq = Bp + (t+1)*32;
            #pragma unroll
            for (int i=0;i<4;i++){
                pa[i] = *(const float4*)(Aq + (size_t)(32*i)*lda);
                pb[i] = *(const float4*)(Bq + (size_t)(32*i)*ldb);
            }
        }
        const uint32_t* Ab = AsBuf[cur] + (wm*64)*LDK;
        const uint32_t* Bb = BsBuf[cur] + (wn*32)*LDK;
        #pragma unroll
        for (int ks=0; ks<4; ks++){
            const int cb = ks*8;
            uint32_t a[4][4], b[4][2];
            #pragma unroll
            for (int mi=0; mi<4; mi++){
                const uint32_t* p = Ab + (mi*16+g)*LDK + cb + tg;
                a[mi][0]=p[0]; a[mi][1]=p[8*LDK]; a[mi][2]=p[4]; a[mi][3]=p[8*LDK+4];
            }
            #pragma unroll
            for (int ni=0; ni<4; ni++){
                const uint32_t* p = Bb + (ni*8+g)*LDK + cb + tg;
                b[ni][0]=p[0]; b[ni][1]=p[4];
            }
            #pragma unroll
            for (int mi=0; mi<4; mi++)
                #pragma unroll
                for (int ni=0; ni<4; ni++)
                    mma8(c[mi][ni], a[mi], b[ni][0], b[ni][1]);
        }
        if (t+1 < nIter){
            const int nxt = cur ^ 1;
            #pragma unroll
            for (int i=0;i<4;i++){
                uint32_t* d = AsBuf[nxt] + (r0+32*i)*LDK + q*4;
                d[0]=f2tf32(pa[i].x); d[1]=f2tf32(pa[i].y); d[2]=f2tf32(pa[i].z); d[3]=f2tf32(pa[i].w);
                uint32_t* e = BsBuf[nxt] + (r0+32*i)*LDK + q*4;
                e[0]=f2tf32(pb[i].x); e[1]=f2tf32(pb[i].y); e[2]=f2tf32(pb[i].z); e[3]=f2tf32(pb[i].w);
            }
        }
        __syncthreads();
    }

    const int rowb = m0 + wm*64, colb = n0 + wn*32;
    #pragma unroll
    for (int mi=0;mi<4;mi++){
        #pragma unroll
        for (int ni=0;ni<4;ni++){
            const int col = colb + ni*8 + tg*2;
            float b0 = 0.f, b1 = 0.f;
            if (bias){ b0 = bias[col]; b1 = bias[col+1]; }
            float* p0 = C + (size_t)(rowb + mi*16 + g)     * ldc + col;
            float* p1 = C + (size_t)(rowb + mi*16 + g + 8) * ldc + col;
            *(float2*)p0 = make_float2(c[mi][ni][0]+b0, c[mi][ni][1]+b1);
            *(float2*)p1 = make_float2(c[mi][ni][2]+b0, c[mi][ni][3]+b1);
        }
    }
}

__global__ __launch_bounds__(256) void proj_kernel(
    const float* __restrict__ x,
    const float* __restrict__ Wq, const float* __restrict__ bq,
    const float* __restrict__ Wk, const float* __restrict__ bk,
    const float* __restrict__ Wv, const float* __restrict__ bv,
    float* Qs, float* Kout, float* Vout)
{
    const float* W; const float* bias; float* C;
    if (blockIdx.x == 0)      { W = Wq; bias = bq; C = Qs;   }
    else if (blockIdx.x == 1) { W = Wk; bias = bk; C = Kout; }
    else                      { W = Wv; bias = bv; C = Vout; }
    gemm_tile_mma(x, DMODEL, W, DMODEL, C, DHEAD, DMODEL, bias, blockIdx.y * 128, 0);
}

__global__ void transpose_v_kernel(const float* __restrict__ V, float* __restrict__ Vt)
{
    __shared__ float tile[32][33];
    const int b  = blockIdx.z;
    const int m0 = blockIdx.x * 32, v0 = blockIdx.y * 32;
    const float* Vb  = V  + (size_t)b * SEQ * DHEAD;
    float*       Vtb = Vt + (size_t)b * DHEAD * SEQ;
    const int tx = threadIdx.x, ty = threadIdx.y;
    #pragma unroll
    for (int i = 0; i < 32; i += 8)
        tile[ty + i][tx] = Vb[(size_t)(m0 + ty + i) * DHEAD + v0 + tx];
    __syncthreads();
    #pragma unroll
    for (int i = 0; i < 32; i += 8)
        Vtb[(size_t)(v0 + ty + i) * SEQ + m0 + tx] = tile[tx][ty + i];
}

// ================= fused flash attention (tf32 mma.sync) =================
// CTA: 128 q-rows, 8 warps x 16 rows. Key tile BN=64. Smem strides = 4 (mod 32).
#define LDKS 132          // Ks row stride (floats)
#define LDVS 68           // Vts row stride
#define LDPS 68           // Ps row stride
#define KS_F   (64*LDKS)          // 8448
#define VT_F   (128*LDVS)         // 8704
#define PS_F   (16*LDPS)          // 1088 per warp
#define SMEM_FLASH ((KS_F + VT_F + 8*PS_F)*4)   // 103424 B

__global__ __launch_bounds__(256, 1) void flash_kernel(
    const float* __restrict__ Qg, const float* __restrict__ Kg,
    const float* __restrict__ Vtg, float* __restrict__ Out)
{
    extern __shared__ float sm[];
    float* Ks  = sm;                  // [64][LDKS] tf32
    float* Vts = sm + KS_F;           // [128][LDVS] tf32 (Vt: [d][key])
    const int tid  = threadIdx.x;
    const int lane = tid & 31;
    const int warp = tid >> 5;
    float* Ps = sm + KS_F + VT_F + warp * PS_F;   // [16][LDPS] warp-private

    const int b  = blockIdx.y;
    const int q0 = blockIdx.x * 128;
    const float* Qb  = Qg  + ((size_t)b*SEQ + q0) * DHEAD;
    const float* Kb  = Kg  + (size_t)b*SEQ*DHEAD;
    const float* Vtb = Vtg + (size_t)b*DHEAD*SEQ;

    const int g  = lane >> 2;
    const int tg = lane & 3;

    // ---- stage Q (pre-scaled, tf32) through Ks; build register fragments ----
    uint32_t Qf[16][4];
    {
        const int r = tid >> 5;            // 0..7
        const int c = (tid & 31) * 4;      // 0..124
        #pragma unroll 1
        for (int ph = 0; ph < 2; ph++) {
            #pragma unroll
            for (int p = 0; p < 8; p++) {
                const int row = p*8 + r;
                float4 v = *(const float4*)(Qb + (size_t)(ph*64 + row)*DHEAD + c);
                uint32_t* d = (uint32_t*)(Ks + row*LDKS + c);
                d[0]=f2tf32(v.x*SCALE); d[1]=f2tf32(v.y*SCALE);
                d[2]=f2tf32(v.z*SCALE); d[3]=f2tf32(v.w*SCALE);
            }
            __syncthreads();
            if ((warp >> 2) == ph) {
                const int rg = (warp & 3) * 16 + g;
                #pragma unroll
                for (int ks = 0; ks < 16; ks++) {
                    const uint32_t* p0 = (const uint32_t*)(Ks + rg*LDKS + ks*8 + tg);
                    const uint32_t* p1 = (const uint32_t*)(Ks + (rg+8)*LDKS + ks*8 + tg);
                    Qf[ks][0] = p0[0];
                    Qf[ks][1] = p1[0];
                    Qf[ks][2] = p0[4];
                    Qf[ks][3] = p1[4];
                }
            }
            __syncthreads();
        }
    }

    // load mappings for K / Vt tiles
    const int kr = tid >> 5,  kc = (tid & 31) * 4;   // K: 8 rows/pass x 128 cols
    const int vr = tid >> 4,  vc = (tid & 15) * 4;   // Vt: 16 rows/pass x 64 cols

    // ---- tile 0 direct load ----
    #pragma unroll
    for (int p = 0; p < 8; p++) {
        float4 v = *(const float4*)(Kb + (size_t)(p*8 + kr)*DHEAD + kc);
        uint32_t* d = (uint32_t*)(Ks + (p*8+kr)*LDKS + kc);
        d[0]=f2tf32(v.x); d[1]=f2tf32(v.y); d[2]=f2tf32(v.z); d[3]=f2tf32(v.w);
    }
    #pragma unroll
    for (int p = 0; p < 8; p++) {
        float4 v = *(const float4*)(Vtb + (size_t)(p*16 + vr)*SEQ + vc);
        uint32_t* d = (uint32_t*)(Vts + (p*16+vr)*LDVS + vc);
        d[0]=f2tf32(v.x); d[1]=f2tf32(v.y); d[2]=f2tf32(v.z); d[3]=f2tf32(v.w);
    }
    __syncthreads();

    float m0 = NEG_INF, m1 = NEG_INF, l0 = 0.f, l1 = 0.f;
    float oa[16][4];
    #pragma unroll
    for (int i=0;i<16;i++){ oa[i][0]=0;oa[i][1]=0;oa[i][2]=0;oa[i][3]=0; }

    #pragma unroll 1
    for (int t = 0; t < SEQ/64; t++) {
        const int kt = t * 64;
        // prefetch next K tile into regs
        float4 kp[8];
        if (t < SEQ/64 - 1) {
            #pragma unroll
            for (int p = 0; p < 8; p++)
                kp[p] = *(const float4*)(Kb + (size_t)(kt+64 + p*8 + kr)*DHEAD + kc);
        }

        // ---- S = Q K^T (scale folded into Q) ----
        float sa[8][4];
        #pragma unroll
        for (int i=0;i<8;i++){ sa[i][0]=0;sa[i][1]=0;sa[i][2]=0;sa[i][3]=0; }
        #pragma unroll
        for (int ks = 0; ks < 16; ks++) {
            #pragma unroll
            for (int ni = 0; ni < 8; ni++) {
                const uint32_t* p = (const uint32_t*)(Ks + (ni*8+g)*LDKS + ks*8 + tg);
                mma8(sa[ni], Qf[ks], p[0], p[4]);
            }
        }

        // ---- online softmax (rows g, g+8 of this warp's 16) ----
        float mx0 = NEG_INF, mx1 = NEG_INF;
        #pragma unroll
        for (int ni = 0; ni < 8; ni++) {
            mx0 = fmaxf(mx0, fmaxf(sa[ni][0], sa[ni][1]));
            mx1 = fmaxf(mx1, fmaxf(sa[ni][2], sa[ni][3]));
        }
        mx0 = fmaxf(mx0, __shfl_xor_sync(~0u, mx0, 1));
        mx0 = fmaxf(mx0, __shfl_xor_sync(~0u, mx0, 2));
        mx1 = fmaxf(mx1, __shfl_xor_sync(~0u, mx1, 1));
        mx1 = fmaxf(mx1, __shfl_xor_sync(~0u, mx1, 2));
        const float nm0 = fmaxf(m0, mx0), nm1 = fmaxf(m1, mx1);
        const float c0 = __expf(m0 - nm0), c1 = __expf(m1 - nm1);
        m0 = nm0; m1 = nm1;
        float rs0 = 0.f, rs1 = 0.f;
        #pragma unroll
        for (int ni = 0; ni < 8; ni++) {
            const float p0 = __expf(sa[ni][0] - nm0);
            const float p1 = __expf(sa[ni][1] - nm0);
            const float p2 = __expf(sa[ni][2] - nm1);
            const float p3 = __expf(sa[ni][3] - nm1);
            rs0 += p0 + p1; rs1 += p2 + p3;
            uint32_t* q  = (uint32_t*)(Ps + g*LDPS + ni*8 + 2*tg);
            uint32_t* q2 = (uint32_t*)(Ps + (g+8)*LDPS + ni*8 + 2*tg);
            q[0]  = f2tf32(p0); q[1]  = f2tf32(p1);
            q2[0] = f2tf32(p2); q2[1] = f2tf32(p3);
        }
        rs0 += __shfl_xor_sync(~0u, rs0, 1); rs0 += __shfl_xor_sync(~0u, rs0, 2);
        rs1 += __shfl_xor_sync(~0u, rs1, 1); rs1 += __shfl_xor_sync(~0u, rs1, 2);
        l0 = l0 * c0 + rs0;  l1 = l1 * c1 + rs1;
        #pragma unroll
        for (int ni = 0; ni < 16; ni++) {
            oa[ni][0] *= c0; oa[ni][1] *= c0;
            oa[ni][2] *= c1; oa[ni][3] *= c1;
        }

        __syncthreads();                       // all warps done reading Ks
        if (t < SEQ/64 - 1) {                  // overwrite Ks with K_{t+1}
            #pragma unroll
            for (int p = 0; p < 8; p++) {
                uint32_t* d = (uint32_t*)(Ks + (p*8+kr)*LDKS + kc);
                d[0]=f2tf32(kp[p].x); d[1]=f2tf32(kp[p].y);
                d[2]=f2tf32(kp[p].z); d[3]=f2tf32(kp[p].w);
            }
        }
        // prefetch next V tile into regs (consumed after PV)
        float4 vp[8];
        if (t < SEQ/64 - 1) {
            #pragma unroll
            for (int p = 0; p < 8; p++)
                vp[p] = *(const float4*)(Vtb + (size_t)(p*16 + vr)*SEQ + kt+64 + vc);
        }

        // ---- O += P V ----
        #pragma unroll
        for (int ks = 0; ks < 8; ks++) {
            uint32_t a[4];
            const uint32_t* pA0 = (const uint32_t*)(Ps + g*LDPS + ks*8 + tg);
            const uint32_t* pA1 = (const uint32_t*)(Ps + (g+8)*LDPS + ks*8 + tg);
            a[0] = pA0[0]; a[1] = pA1[0]; a[2] = pA0[4]; a[3] = pA1[4];
            #pragma unroll
            for (int ni = 0; ni < 16; ni++) {
                const uint32_t* p = (const uint32_t*)(Vts + (ni*8+g)*LDVS + ks*8 + tg);
                mma8(oa[ni], a, p[0], p[4]);
            }
        }

        __syncthreads();                       // all warps done reading Vts
        if (t < SEQ/64 - 1) {
            #pragma unroll
            for (int p = 0; p < 8; p++) {
                uint32_t* d = (uint32_t*)(Vts + (p*16+vr)*LDVS + vc);
                d[0]=f2tf32(vp[p].x); d[1]=f2tf32(vp[p].y);
                d[2]=f2tf32(vp[p].z); d[3]=f2tf32(vp[p].w);
            }
        }
    }

    // ---- epilogue: out = NBLOCKS * O / l ----
    const float f0 = NBLOCKS / l0, f1 = NBLOCKS / l1;
    const int qr = q0 + warp*16 + g;
    float* Ob = Out + (size_t)b*SEQ*DHEAD;
    #pragma unroll
    for (int ni = 0; ni < 16; ni++) {
        const int col = ni*8 + 2*tg;
        *(float2*)(Ob + (size_t)qr*DHEAD + col)     = make_float2(oa[ni][0]*f0, oa[ni][1]*f0);
        *(float2*)(Ob + (size_t)(qr+8)*DHEAD + col) = make_float2(oa[ni][2]*f1, oa[ni][3]*f1);
    }
}

// ================= launch =================
extern "C" void kernel_launch(void* const* d_in, const int* in_sizes, int n_in,
                              void* d_out, int out_size)
{
    const float* x  = (const float*)d_in[0];
    const float* Wq = (const float*)d_in[1];
    const float* bq = (const float*)d_in[2];
    const float* Wk = (const float*)d_in[3];
    const float* bk = (const float*)d_in[4];
    const float* Wv = (const float*)d_in[5];
    const float* bv = (const float*)d_in[6];

    float* out = (float*)d_out;
    float *qs, *vt, *gkv;
    cudaGetSymbolAddress((void**)&qs,  g_Q);
    cudaGetSymbolAddress((void**)&vt,  g_Vt);
    cudaGetSymbolAddress((void**)&gkv, g_KV);

    float *Kout, *Vout;
    if (out_size >= 3 * NPER) { Kout = out + NPER; Vout = out + 2 * NPER; }
    else                      { Kout = gkv;        Vout = gkv + NPER;     }

    cudaFuncSetAttribute(proj_kernel,  cudaFuncAttributeMaxDynamicSharedMemorySize, SMEM_PROJ);
    cudaFuncSetAttribute(flash_kernel, cudaFuncAttributeMaxDynamicSharedMemorySize, SMEM_FLASH);

    // 1) QKV projection
    proj_kernel<<<dim3(3, 128, 1), 256, SMEM_PROJ>>>(x, Wq, bq, Wk, bk, Wv, bv,
                                                     qs, Kout, Vout);
    // 2) V transpose -> [b][d][m]
    transpose_v_kernel<<<dim3(SEQ/32, DHEAD/32, BATCH), dim3(32, 8)>>>(Vout, vt);
    // 3) fused attention: out = NBLOCKS * softmax(QK^T * scale) V
    flash_kernel<<<dim3(SEQ/128, BATCH), 256, SMEM_FLASH>>>(qs, Kout, vt, out);
}